// round 3
// baseline (speedup 1.0000x reference)
#include <cuda_runtime.h>
#include <math.h>

#define NB 1024
#define NC 100000
#define THREADS 256

// scratch: per-row NLL + completion counter (zero-initialized at load)
static __device__ float g_nll[NB];
static __device__ unsigned int g_done;

__device__ __forceinline__ float ex2_fast(float x) {
    float y;
    asm("ex2.approx.ftz.f32 %0, %1;" : "=f"(y) : "f"(x));
    return y;
}

__device__ __forceinline__ float4 ldcs4(const float4* p) {
    float4 v;
    asm("ld.global.cs.v4.f32 {%0,%1,%2,%3}, [%4];"
        : "=f"(v.x), "=f"(v.y), "=f"(v.z), "=f"(v.w) : "l"(p));
    return v;
}

// 64 * log2(e)
#define K2 92.33248261625200f
#define LOG2E 1.4426950408889634f

__device__ __forceinline__ float term(float v) {
    float c = fminf(fmaxf(v, -1.0f), 1.0f);
    return ex2_fast(fmaf(c, K2, -K2));   // exp(64*c - 64)
}

__global__ void __launch_bounds__(THREADS)
fused_loss_kernel(const float* __restrict__ x,
                  const int* __restrict__ label,
                  const float* __restrict__ margin,
                  float* __restrict__ out) {
    const int row = blockIdx.x;
    const float4* __restrict__ p =
        reinterpret_cast<const float4*>(x + (size_t)row * NC);
    const int n4 = NC / 4;  // 25000

    float s = 0.0f;
    #pragma unroll 8
    for (int i = threadIdx.x; i < n4; i += THREADS) {
        float4 v = ldcs4(p + i);
        s += term(v.x) + term(v.y) + term(v.z) + term(v.w);
    }

    // block reduction
    __shared__ float red[THREADS / 32];
    __shared__ bool amLast;
    const int lane = threadIdx.x & 31;
    const int wid  = threadIdx.x >> 5;
    #pragma unroll
    for (int o = 16; o; o >>= 1) s += __shfl_xor_sync(0xFFFFFFFFu, s, o);
    if (lane == 0) red[wid] = s;
    __syncthreads();

    if (threadIdx.x == 0) {
        float t = 0.0f;
        #pragma unroll
        for (int w = 0; w < THREADS / 32; w++) t += red[w];

        int lb = label[row];
        const bool valid = (lb >= 0);
        int tgt = valid ? lb : 0;
        tgt = min(max(tgt, 0), NC - 1);           // never fabricate OOB address
        const float mg = valid ? margin[row] : 0.0f;

        float xt = x[(size_t)row * NC + tgt];
        float c  = fminf(fmaxf(xt, -1.0f), 1.0f);
        float l_mod = 64.0f * cosf(acosf(c) + mg);

        // replace target term: subtract original, add modified
        float stot = t - ex2_fast(fmaf(c, K2, -K2))
                       + ex2_fast((l_mod - 64.0f) * LOG2E);

        g_nll[row] = 64.0f + logf(stot) - l_mod;  // nll = 64 + log(S) - l_mod

        __threadfence();
        unsigned int done = atomicAdd(&g_done, 1u);
        amLast = (done == (unsigned int)(NB - 1));
    }
    __syncthreads();

    // last block to finish reduces all per-row NLLs (deterministic tree order)
    if (amLast) {
        __threadfence();
        float t = 0.0f;
        #pragma unroll
        for (int k = 0; k < NB / THREADS; k++)
            t += g_nll[threadIdx.x + k * THREADS];

        #pragma unroll
        for (int o = 16; o; o >>= 1) t += __shfl_xor_sync(0xFFFFFFFFu, t, o);
        if (lane == 0) red[wid] = t;
        __syncthreads();
        if (wid == 0) {
            float u = (lane < THREADS / 32) ? red[lane] : 0.0f;
            #pragma unroll
            for (int o = (THREADS / 64); o; o >>= 1)
                u += __shfl_xor_sync(0xFFFFFFFFu, u, o);
            if (lane == 0) {
                out[0] = u * (1.0f / (float)NB);
                g_done = 0;                        // reset for next graph replay
            }
        }
    }
}

extern "C" void kernel_launch(void* const* d_in, const int* in_sizes, int n_in,
                              void* d_out, int out_size) {
    const float* x      = (const float*)d_in[0];
    const int*   label  = (const int*)d_in[1];
    const float* margin = (const float*)d_in[2];
    float*       out    = (float*)d_out;

    fused_loss_kernel<<<NB, THREADS>>>(x, label, margin, out);
}